// round 13
// baseline (speedup 1.0000x reference)
#include <cuda_runtime.h>

static constexpr int AB    = 128;    // A*B
static constexpr int NROWS = 1024;   // N = M
static constexpr int KD    = 64;
static constexpr int RQ    = KD / 4; // float4 per row = 16
static constexpr int CHV   = 4;      // v-sum chunks per ab (256 rows each)
static constexpr int CHU   = 8;      // gate chunks per ab (128 rows each)
static constexpr int G     = 8;      // pipeline groups
static constexpr int GPB   = AB / G; // abs per group = 16

// Block ranges within one step launch
static constexpr int NB_VS = GPB * CHV;          // 64  vsum blocks
static constexpr int NB_GU = GPB * CHU;          // 128 gate-u blocks
static constexpr int NB_GV = GPB * CHU;          // 128 gate-v blocks
static constexpr int NB_ALL = NB_VS + NB_GU + NB_GV;  // 320

// Partial column sums (fixed-order, deterministic; written/consumed across
// sequential launches — no intra-kernel races)
__device__ float4 g_part_v[AB * CHV * RQ];
__device__ float4 g_part_u[AB * CHU * RQ];

// ---------------------------------------------------------------------------
// One pipeline step. Roles by blockIdx range:
//   [0,64)    vsum on group gv      (pure read of v slice)
//   [64,192)  gate-u + u-sum on gu  (read u slice, write gated u)
//   [192,320) gate-v on gw          (read v slice [L2-hot], write gated v)
// Out-of-range group => early exit (pipeline fill/drain).
// ---------------------------------------------------------------------------
__global__ void __launch_bounds__(256)
step_kernel(const float4* __restrict__ u,
            const float4* __restrict__ v,
            float4* __restrict__ out,
            int gv, int gu, int gw) {
    const int blk = blockIdx.x;
    const int tid = threadIdx.x;
    __shared__ float4 sred[16][16];

    if (blk < NB_VS) {
        // ── vsum role (R4 config: 256-row chunk, MLP=16) ──
        if (gv < 0 || gv >= G) return;
        const int ab    = gv * GPB + (blk >> 2);
        const int chunk = blk & 3;
        const float4* __restrict__ base =
            v + ((size_t)ab * NROWS + chunk * 256) * RQ;

        const int q = tid & 15;
        const int r = tid >> 4;            // 0..15

        float4 s = make_float4(0.f, 0.f, 0.f, 0.f);
#pragma unroll
        for (int i = 0; i < 16; i++) {
            const float4 x = base[(size_t)(r + i * 16) * RQ + q];
            s.x += x.x; s.y += x.y; s.z += x.z; s.w += x.w;
        }
        sred[r][q] = s;
        __syncthreads();
#pragma unroll
        for (int stride = 8; stride > 0; stride >>= 1) {
            if (r < stride) {
                const float4 o = sred[r + stride][q];
                sred[r][q].x += o.x; sred[r][q].y += o.y;
                sred[r][q].z += o.z; sred[r][q].w += o.w;
            }
            __syncthreads();
        }
        if (r == 0) g_part_v[(ab * CHV + chunk) * RQ + q] = sred[0][q];

    } else if (blk < NB_VS + NB_GU) {
        // ── gate-u + u-sum role ──
        if (gu < 0 || gu >= G) return;
        const int lblk  = blk - NB_VS;
        const int ab    = gu * GPB + (lblk >> 3);
        const int chunk = lblk & 7;
        const int warp  = tid >> 5, lane = tid & 31;
        const int half  = lane >> 4, q = lane & 15;

        const float4* __restrict__ Pv = g_part_v + (size_t)ab * CHV * RQ + q;
        float4 sv = __ldg(Pv);
#pragma unroll
        for (int c = 1; c < CHV; c++) {
            const float4 o = __ldg(Pv + c * RQ);
            sv.x += o.x; sv.y += o.y; sv.z += o.z; sv.w += o.w;
        }

        const int    row0 = ab * NROWS + chunk * 128 + warp * 16;
        const size_t base = (size_t)row0 * RQ + (size_t)half * RQ + q;

        float4 x[8];
#pragma unroll
        for (int j = 0; j < 8; j++) x[j] = __ldcs(u + base + (size_t)j * (2 * RQ));

        // u-sum partial: fold 8 slots, then the two 16-lane halves
        float4 cs = make_float4(0.f, 0.f, 0.f, 0.f);
#pragma unroll
        for (int j = 0; j < 8; j++) {
            cs.x += x[j].x; cs.y += x[j].y; cs.z += x[j].z; cs.w += x[j].w;
        }
        cs.x += __shfl_xor_sync(0xffffffffu, cs.x, 16);
        cs.y += __shfl_xor_sync(0xffffffffu, cs.y, 16);
        cs.z += __shfl_xor_sync(0xffffffffu, cs.z, 16);
        cs.w += __shfl_xor_sync(0xffffffffu, cs.w, 16);
        if (half == 0) sred[warp][q] = cs;
        __syncthreads();
        if (tid < 16) {                    // serial 8-term fixed-order fold
            float4 a = sred[0][q];
#pragma unroll
            for (int wg = 1; wg < 8; wg++) {
                const float4 o = sred[wg][q];
                a.x += o.x; a.y += o.y; a.z += o.z; a.w += o.w;
            }
            g_part_u[(ab * CHU + chunk) * RQ + q] = a;
        }

        // gate: row dot vs sv, 4-level xor tree inside the 16-lane segment
        float p[8];
#pragma unroll
        for (int j = 0; j < 8; j++)
            p[j] = fmaf(x[j].x, sv.x,
                    fmaf(x[j].y, sv.y,
                     fmaf(x[j].z, sv.z, x[j].w * sv.w)));
#pragma unroll
        for (int m = 8; m; m >>= 1)
#pragma unroll
            for (int j = 0; j < 8; j++)
                p[j] += __shfl_xor_sync(0xffffffffu, p[j], m);
#pragma unroll
        for (int j = 0; j < 8; j++) {
            const float g = (p[j] > 0.f) ? 1.f : 0.f;
            __stcs(out + base + (size_t)j * (2 * RQ),
                   make_float4(x[j].x * g, x[j].y * g, x[j].z * g, x[j].w * g));
        }

    } else {
        // ── gate-v role ──
        if (gw < 0 || gw >= G) return;
        const int lblk  = blk - NB_VS - NB_GU;
        const int ab    = gw * GPB + (lblk >> 3);
        const int chunk = lblk & 7;
        const int warp  = tid >> 5, lane = tid & 31;
        const int half  = lane >> 4, q = lane & 15;
        float4* __restrict__ outv = out + (size_t)AB * NROWS * RQ;

        const float4* __restrict__ Pu = g_part_u + (size_t)ab * CHU * RQ + q;
        float4 su = __ldg(Pu);
#pragma unroll
        for (int c = 1; c < CHU; c++) {
            const float4 o = __ldg(Pu + c * RQ);
            su.x += o.x; su.y += o.y; su.z += o.z; su.w += o.w;
        }

        const int    row0 = ab * NROWS + chunk * 128 + warp * 16;
        const size_t base = (size_t)row0 * RQ + (size_t)half * RQ + q;

        float4 x[8];
#pragma unroll
        for (int j = 0; j < 8; j++) x[j] = __ldcs(v + base + (size_t)j * (2 * RQ));

        float p[8];
#pragma unroll
        for (int j = 0; j < 8; j++)
            p[j] = fmaf(x[j].x, su.x,
                    fmaf(x[j].y, su.y,
                     fmaf(x[j].z, su.z, x[j].w * su.w)));
#pragma unroll
        for (int m = 8; m; m >>= 1)
#pragma unroll
            for (int j = 0; j < 8; j++)
                p[j] += __shfl_xor_sync(0xffffffffu, p[j], m);
#pragma unroll
        for (int j = 0; j < 8; j++) {
            const float g = (p[j] > 0.f) ? 1.f : 0.f;
            __stcs(outv + base + (size_t)j * (2 * RQ),
                   make_float4(x[j].x * g, x[j].y * g, x[j].z * g, x[j].w * g));
        }
    }
}

// ---------------------------------------------------------------------------
extern "C" void kernel_launch(void* const* d_in, const int* in_sizes, int n_in,
                              void* d_out, int out_size) {
    const float4* u = (const float4*)d_in[0];
    const float4* v = (const float4*)d_in[1];
    float4* out = (float4*)d_out;

    // Software pipeline over ab-groups; kernel boundaries enforce deps.
    for (int s = 0; s < G + 2; s++) {
        step_kernel<<<NB_ALL, 256>>>(u, v, out, s, s - 1, s - 2);
    }
}

// round 15
// speedup vs baseline: 1.6641x; 1.6641x over previous
#include <cuda_runtime.h>

static constexpr int AB    = 128;    // A*B
static constexpr int NROWS = 1024;   // N = M
static constexpr int KD    = 64;
static constexpr int RQ    = KD / 4; // float4 per row = 16
static constexpr int CHV   = 4;      // v-sum chunks per ab (256 rows each)
static constexpr int CHU   = 8;      // gate chunks per ab (128 rows each)

static constexpr int NB_VS = AB * CHV;               // 512
static constexpr int NB_GU = AB * CHU;               // 1024
static constexpr int NB_GV = AB * CHU;               // 1024
static constexpr int NB_ALL = NB_VS + NB_GU + NB_GV; // 2560

// Partial column sums (fixed-order, deterministic)
__device__ float4 g_part_v[AB * CHV * RQ];
__device__ float4 g_part_u[AB * CHU * RQ];
// Per-ab completion counters (progress only; reset per call by prologue)
__device__ int g_vcnt[AB];
__device__ int g_ucnt[AB];

__global__ void reset_kernel() {
    if (threadIdx.x < AB) { g_vcnt[threadIdx.x] = 0; g_ucnt[threadIdx.x] = 0; }
}

// L2-coherent counter read (no .nc staleness, no L1).
__device__ __forceinline__ int ld_cg_int(const int* p) {
    int r;
    asm volatile("ld.global.cg.s32 %0, [%1];" : "=r"(r) : "l"(p) : "memory");
    return r;
}
// L2-coherent float4 load for same-launch produced partials.
__device__ __forceinline__ float4 ld_cg_f4(const float4* p) {
    float4 r;
    asm volatile("ld.global.cg.v4.f32 {%0,%1,%2,%3}, [%4];"
                 : "=f"(r.x), "=f"(r.y), "=f"(r.z), "=f"(r.w)
                 : "l"(p) : "memory");
    return r;
}

__device__ __forceinline__ void wait_cnt(const int* cnt, int target) {
    while (ld_cg_int(cnt) < target) __nanosleep(128);
}

// ---------------------------------------------------------------------------
// Single fused launch. Role by blockIdx (one work item per block, then exit):
//   [0,512)      vsum chunk      — never waits; lowest IDs => wave-1 resident
//   [512,1536)   gate-u chunk    — waits for its ab's 4 v-partials
//   [1536,2560)  gate-v chunk    — waits for its ab's 8 u-partials
// ---------------------------------------------------------------------------
__global__ void __launch_bounds__(256)
fused_kernel(const float4* __restrict__ u,
             const float4* __restrict__ v,
             float4* __restrict__ out) {
    const int blk = blockIdx.x;
    const int tid = threadIdx.x;
    __shared__ float4 sred[16][16];

    if (blk < NB_VS) {
        // ── vsum: one 256-row chunk of v (R4-proven config, MLP=16) ──
        const int ab    = blk >> 2;
        const int chunk = blk & 3;
        const float4* __restrict__ base =
            v + ((size_t)ab * NROWS + chunk * 256) * RQ;

        const int q = tid & 15;
        const int r = tid >> 4;            // 0..15

        float4 s = make_float4(0.f, 0.f, 0.f, 0.f);
#pragma unroll
        for (int i = 0; i < 16; i++) {
            const float4 x = base[(size_t)(r + i * 16) * RQ + q];
            s.x += x.x; s.y += x.y; s.z += x.z; s.w += x.w;
        }
        sred[r][q] = s;
        __syncthreads();
#pragma unroll
        for (int stride = 8; stride > 0; stride >>= 1) {
            if (r < stride) {
                const float4 o = sred[r + stride][q];
                sred[r][q].x += o.x; sred[r][q].y += o.y;
                sred[r][q].z += o.z; sred[r][q].w += o.w;
            }
            __syncthreads();
        }
        if (r == 0) g_part_v[(ab * CHV + chunk) * RQ + q] = sred[0][q];
        __syncthreads();
        if (tid == 0) { __threadfence(); atomicAdd(&g_vcnt[ab], 1); }

    } else if (blk < NB_VS + NB_GU) {
        // ── gate-u + u-sum partial: one 128-row chunk of u ──
        const int lblk  = blk - NB_VS;
        const int ab    = lblk >> 3;
        const int chunk = lblk & 7;
        const int warp  = tid >> 5, lane = tid & 31;
        const int half  = lane >> 4, q = lane & 15;

        if (tid == 0) { wait_cnt(&g_vcnt[ab], CHV); __threadfence(); }
        __syncthreads();                    // block-wide acquire point

        // v_sum[ab]: L2-coherent loads (produced THIS launch — no .nc!)
        const float4* Pv = g_part_v + (size_t)ab * CHV * RQ + q;
        float4 sv = ld_cg_f4(Pv);
#pragma unroll
        for (int c = 1; c < CHV; c++) {
            const float4 o = ld_cg_f4(Pv + c * RQ);
            sv.x += o.x; sv.y += o.y; sv.z += o.z; sv.w += o.w;
        }

        const int    row0 = ab * NROWS + chunk * 128 + warp * 16;
        const size_t base = (size_t)row0 * RQ + (size_t)half * RQ + q;

        float4 x[8];
#pragma unroll
        for (int j = 0; j < 8; j++) x[j] = __ldcs(u + base + (size_t)j * (2 * RQ));

        // u-sum partial first, signal EARLY so gate-v unblocks ASAP
        float4 cs = make_float4(0.f, 0.f, 0.f, 0.f);
#pragma unroll
        for (int j = 0; j < 8; j++) {
            cs.x += x[j].x; cs.y += x[j].y; cs.z += x[j].z; cs.w += x[j].w;
        }
        cs.x += __shfl_xor_sync(0xffffffffu, cs.x, 16);
        cs.y += __shfl_xor_sync(0xffffffffu, cs.y, 16);
        cs.z += __shfl_xor_sync(0xffffffffu, cs.z, 16);
        cs.w += __shfl_xor_sync(0xffffffffu, cs.w, 16);
        if (half == 0) sred[warp][q] = cs;
        __syncthreads();
        if (tid < 16) {                     // serial 8-term fixed-order fold
            float4 a = sred[0][q];
#pragma unroll
            for (int wg = 1; wg < 8; wg++) {
                const float4 o = sred[wg][q];
                a.x += o.x; a.y += o.y; a.z += o.z; a.w += o.w;
            }
            g_part_u[(ab * CHU + chunk) * RQ + q] = a;
        }
        __syncthreads();
        if (tid == 0) { __threadfence(); atomicAdd(&g_ucnt[ab], 1); }

        // gate: row dot vs sv, 4-level xor tree inside the 16-lane segment
        float p[8];
#pragma unroll
        for (int j = 0; j < 8; j++)
            p[j] = fmaf(x[j].x, sv.x,
                    fmaf(x[j].y, sv.y,
                     fmaf(x[j].z, sv.z, x[j].w * sv.w)));
#pragma unroll
        for (int m = 8; m; m >>= 1)
#pragma unroll
            for (int j = 0; j < 8; j++)
                p[j] += __shfl_xor_sync(0xffffffffu, p[j], m);
#pragma unroll
        for (int j = 0; j < 8; j++) {
            const float g = (p[j] > 0.f) ? 1.f : 0.f;
            __stcs(out + base + (size_t)j * (2 * RQ),
                   make_float4(x[j].x * g, x[j].y * g, x[j].z * g, x[j].w * g));
        }

    } else {
        // ── gate-v: one 128-row chunk of v (L2-hot from vsum) ──
        const int lblk  = blk - NB_VS - NB_GU;
        const int ab    = lblk >> 3;
        const int chunk = lblk & 7;
        const int warp  = tid >> 5, lane = tid & 31;
        const int half  = lane >> 4, q = lane & 15;
        float4* __restrict__ outv = out + (size_t)AB * NROWS * RQ;

        if (tid == 0) { wait_cnt(&g_ucnt[ab], CHU); __threadfence(); }
        __syncthreads();                    // block-wide acquire point

        const float4* Pu = g_part_u + (size_t)ab * CHU * RQ + q;
        float4 su = ld_cg_f4(Pu);
#pragma unroll
        for (int c = 1; c < CHU; c++) {
            const float4 o = ld_cg_f4(Pu + c * RQ);
            su.x += o.x; su.y += o.y; su.z += o.z; su.w += o.w;
        }

        const int    row0 = ab * NROWS + chunk * 128 + warp * 16;
        const size_t base = (size_t)row0 * RQ + (size_t)half * RQ + q;

        float4 x[8];
#pragma unroll
        for (int j = 0; j < 8; j++) x[j] = __ldcs(v + base + (size_t)j * (2 * RQ));

        float p[8];
#pragma unroll
        for (int j = 0; j < 8; j++)
            p[j] = fmaf(x[j].x, su.x,
                    fmaf(x[j].y, su.y,
                     fmaf(x[j].z, su.z, x[j].w * su.w)));
#pragma unroll
        for (int m = 8; m; m >>= 1)
#pragma unroll
            for (int j = 0; j < 8; j++)
                p[j] += __shfl_xor_sync(0xffffffffu, p[j], m);
#pragma unroll
        for (int j = 0; j < 8; j++) {
            const float g = (p[j] > 0.f) ? 1.f : 0.f;
            __stcs(outv + base + (size_t)j * (2 * RQ),
                   make_float4(x[j].x * g, x[j].y * g, x[j].z * g, x[j].w * g));
        }
    }
}

// ---------------------------------------------------------------------------
extern "C" void kernel_launch(void* const* d_in, const int* in_sizes, int n_in,
                              void* d_out, int out_size) {
    const float4* u = (const float4*)d_in[0];
    const float4* v = (const float4*)d_in[1];

    reset_kernel<<<1, 128>>>();
    fused_kernel<<<NB_ALL, 256>>>(u, v, (float4*)d_out);
}